// round 7
// baseline (speedup 1.0000x reference)
#include <cuda_runtime.h>
#include <cstdint>
#include <cstddef>

// Problem constants (static in reference)
constexpr int Mm = 512, Nn = 4096, Kdim = 4096, Dd = 128, Hh = 32, Ll = 4096, Pp = 3584;
constexpr size_t OUT0 = (size_t)Mm * Nn;

// Scratch (device globals: allocation-free per harness rules)
__device__ float g_q [(size_t)Hh * Mm * Dd];   // 8 MB [H][M][D]
__device__ float g_Kn[(size_t)Hh * Mm * Dd];   // 8 MB new K rows [H][M][D]
__device__ float g_Vn[(size_t)Hh * Mm * Dd];   // 8 MB new V rows [H][M][D]
__device__ float g_S [(size_t)Hh * Mm * Ll];   // 256 MB raw scores [H*M][L]
__device__ float g_invs[Hh * Mm];              // 1/sum(exp(s)) per row

// ---------------------------------------------------------------------------
// TF32 helpers (baseline PTX only — no sm_103a-suffixed features)
// ---------------------------------------------------------------------------
__device__ __forceinline__ void tf32split(float f, uint32_t& hi, uint32_t& lo) {
    asm("cvt.rna.tf32.f32 %0, %1;" : "=r"(hi) : "f"(f));
    float r = f - __uint_as_float(hi);
    asm("cvt.rna.tf32.f32 %0, %1;" : "=r"(lo) : "f"(r));
}

__device__ __forceinline__ void mma8(float* c, const uint32_t* a, const uint32_t* b) {
    asm("mma.sync.aligned.m16n8k8.row.col.f32.tf32.tf32.f32 "
        "{%0,%1,%2,%3}, {%4,%5,%6,%7}, {%8,%9}, {%0,%1,%2,%3};"
        : "+f"(c[0]), "+f"(c[1]), "+f"(c[2]), "+f"(c[3])
        : "r"(a[0]), "r"(a[1]), "r"(a[2]), "r"(a[3]), "r"(b[0]), "r"(b[1]));
}

// ---------------------------------------------------------------------------
// SMEM layout (uint32 words), per buffer:
//   Ahi [128][20] @ 0     Alo [128][20] @ 2560
//   Bhi [16][136] @ 5120  Blo [16][136] @ 7296
// Double buffered. Pre-split tf32 hi/lo => inner loop is pure LDS + MMA.
// Fragment LDS is bank-conflict-free with these strides (A:20, B:136).
// ---------------------------------------------------------------------------
#define A_STR 20
#define B_STR 136
#define AH_O 0
#define AL_O 2560
#define BH_O 5120
#define BL_O 7296
#define BUF_W 9472
constexpr int SMEMSZ = 2 * BUF_W * 4;   // 75776 B

// B rows come from two sources split at row `split` (cache vs freshly-projected)
struct BSrc { const float* p0; const float* p1; int split; size_t ld; };
__device__ __forceinline__ const float* brow(const BSrc& s, int r) {
    return (r < s.split) ? s.p0 + (size_t)r * s.ld : s.p1 + (size_t)(r - s.split) * s.ld;
}

struct F8 { float v[8]; };

template <bool EXPA>
__device__ __forceinline__ F8 fetchA(const float* __restrict__ A, size_t lda,
                                     int am0, int kb, int tid) {
    int r = tid >> 1, kq = (tid & 1) * 8;
    const float* p = A + (size_t)(am0 + r) * lda + kb + kq;
    float4 a = *(const float4*)p, b = *(const float4*)(p + 4);
    F8 o;
    o.v[0] = a.x; o.v[1] = a.y; o.v[2] = a.z; o.v[3] = a.w;
    o.v[4] = b.x; o.v[5] = b.y; o.v[6] = b.z; o.v[7] = b.w;
    if (EXPA) {
#pragma unroll
        for (int j = 0; j < 8; j++) o.v[j] = __expf(o.v[j]);
    }
    return o;
}
__device__ __forceinline__ void stA(uint32_t* buf, const F8& o, int tid) {
    int r = tid >> 1, kq = (tid & 1) * 8;
    uint32_t h[8], l[8];
#pragma unroll
    for (int j = 0; j < 8; j++) tf32split(o.v[j], h[j], l[j]);
    uint32_t* ph = buf + AH_O + r * A_STR + kq;
    uint32_t* pl = buf + AL_O + r * A_STR + kq;
    *(uint4*)ph = make_uint4(h[0], h[1], h[2], h[3]);
    *(uint4*)(ph + 4) = make_uint4(h[4], h[5], h[6], h[7]);
    *(uint4*)pl = make_uint4(l[0], l[1], l[2], l[3]);
    *(uint4*)(pl + 4) = make_uint4(l[4], l[5], l[6], l[7]);
}

// direct B: smem[k][n] = B[k0+k][bn0+n]
__device__ __forceinline__ F8 fetchBd(const BSrc& s, int bn0, int k0, int tid) {
    int k = tid >> 4, n0 = (tid & 15) * 8;
    const float* p = brow(s, k0 + k) + bn0 + n0;
    float4 a = *(const float4*)p, b = *(const float4*)(p + 4);
    F8 o;
    o.v[0] = a.x; o.v[1] = a.y; o.v[2] = a.z; o.v[3] = a.w;
    o.v[4] = b.x; o.v[5] = b.y; o.v[6] = b.z; o.v[7] = b.w;
    return o;
}
__device__ __forceinline__ void stBd(uint32_t* buf, const F8& o, int tid) {
    int k = tid >> 4, n0 = (tid & 15) * 8;
    uint32_t h[8], l[8];
#pragma unroll
    for (int j = 0; j < 8; j++) tf32split(o.v[j], h[j], l[j]);
    uint32_t* ph = buf + BH_O + k * B_STR + n0;
    uint32_t* pl = buf + BL_O + k * B_STR + n0;
    *(uint4*)ph = make_uint4(h[0], h[1], h[2], h[3]);
    *(uint4*)(ph + 4) = make_uint4(h[4], h[5], h[6], h[7]);
    *(uint4*)pl = make_uint4(l[0], l[1], l[2], l[3]);
    *(uint4*)(pl + 4) = make_uint4(l[4], l[5], l[6], l[7]);
}

// transposed B: smem[k][n] = B[bn0+n][kb+k]  (scores: K-cache is [l][d])
__device__ __forceinline__ F8 fetchBt(const BSrc& s, int bn0, int kb, int tid) {
    int l = tid >> 1, dq = (tid & 1) * 8;
    const float* p = brow(s, bn0 + l) + kb + dq;
    float4 a = *(const float4*)p, b = *(const float4*)(p + 4);
    F8 o;
    o.v[0] = a.x; o.v[1] = a.y; o.v[2] = a.z; o.v[3] = a.w;
    o.v[4] = b.x; o.v[5] = b.y; o.v[6] = b.z; o.v[7] = b.w;
    return o;
}
__device__ __forceinline__ void stBt(uint32_t* buf, const F8& o, int tid) {
    int l = tid >> 1, dq = (tid & 1) * 8;
#pragma unroll
    for (int j = 0; j < 8; j++) {
        uint32_t h, lo;
        tf32split(o.v[j], h, lo);
        buf[BH_O + (dq + j) * B_STR + l] = h;
        buf[BL_O + (dq + j) * B_STR + l] = lo;
    }
}

// ---------------------------------------------------------------------------
// GEMM core: C[128,128] = A[128xK] * B[Kx128]; 8 warps (4M x 2N), warp 32x64.
// 3xTF32 passes: ah*bh + ah*bl + al*bh. Split done at stage time only.
// ---------------------------------------------------------------------------
template <int NCHUNK, bool BTRANS, bool EXPA>
__device__ __forceinline__ void gemm_tc(const float* __restrict__ A, size_t lda, int am0,
                                        BSrc bs, int bn0,
                                        uint32_t* sm, float (&acc)[2][8][4]) {
    const int tid = threadIdx.x;
    const int lane = tid & 31, wid = tid >> 5;
    const int wm0 = (wid >> 1) * 32, wn0 = (wid & 1) * 64;
    const int g = lane >> 2, t4 = lane & 3;

#pragma unroll
    for (int i = 0; i < 2; i++)
#pragma unroll
        for (int j = 0; j < 8; j++)
#pragma unroll
            for (int q = 0; q < 4; q++) acc[i][j][q] = 0.f;

    F8 ra = fetchA<EXPA>(A, lda, am0, 0, tid);
    F8 rb = BTRANS ? fetchBt(bs, bn0, 0, tid) : fetchBd(bs, bn0, 0, tid);

#pragma unroll 1
    for (int c = 0; c < NCHUNK; c++) {
        uint32_t* buf = sm + (c & 1) * BUF_W;
        stA(buf, ra, tid);
        if (BTRANS) stBt(buf, rb, tid); else stBd(buf, rb, tid);
        __syncthreads();
        if (c + 1 < NCHUNK) {
            ra = fetchA<EXPA>(A, lda, am0, (c + 1) * 16, tid);
            rb = BTRANS ? fetchBt(bs, bn0, (c + 1) * 16, tid)
                        : fetchBd(bs, bn0, (c + 1) * 16, tid);
        }
        const uint32_t* Ah = buf + AH_O;
        const uint32_t* Al = buf + AL_O;
        const uint32_t* Bh = buf + BH_O;
        const uint32_t* Bl = buf + BL_O;
#pragma unroll
        for (int kt = 0; kt < 2; kt++) {
            const int kc = kt * 8 + t4;
            uint32_t ah[2][4], al[2][4];
#pragma unroll
            for (int i = 0; i < 2; i++) {
                int r0 = (wm0 + i * 16 + g) * A_STR + kc;
                ah[i][0] = Ah[r0];               al[i][0] = Al[r0];
                ah[i][1] = Ah[r0 + 8 * A_STR];   al[i][1] = Al[r0 + 8 * A_STR];
                ah[i][2] = Ah[r0 + 4];           al[i][2] = Al[r0 + 4];
                ah[i][3] = Ah[r0 + 8 * A_STR + 4]; al[i][3] = Al[r0 + 8 * A_STR + 4];
            }
#pragma unroll
            for (int j = 0; j < 8; j++) {
                int nb = kc * B_STR + wn0 + j * 8 + g;
                uint32_t bh[2] = { Bh[nb], Bh[nb + 4 * B_STR] };
                uint32_t bl[2] = { Bl[nb], Bl[nb + 4 * B_STR] };
#pragma unroll
                for (int i = 0; i < 2; i++) {
                    mma8(acc[i][j], ah[i], bh);
                    mma8(acc[i][j], ah[i], bl);
                    mma8(acc[i][j], al[i], bh);
                }
            }
        }
        __syncthreads();
    }
}

__device__ __forceinline__ void store_acc(float (&acc)[2][8][4], float* __restrict__ dst,
                                          size_t ldd, const float* __restrict__ rowscale) {
    const int tid = threadIdx.x;
    const int lane = tid & 31, wid = tid >> 5;
    const int wm0 = (wid >> 1) * 32, wn0 = (wid & 1) * 64;
    const int g = lane >> 2, t4 = lane & 3;
#pragma unroll
    for (int i = 0; i < 2; i++) {
        int r0 = wm0 + i * 16 + g;
        float s0 = rowscale ? rowscale[r0] : 1.f;
        float s1 = rowscale ? rowscale[r0 + 8] : 1.f;
#pragma unroll
        for (int j = 0; j < 8; j++) {
            int cn = wn0 + j * 8 + t4 * 2;
            *(float2*)&dst[(size_t)r0 * ldd + cn] =
                make_float2(acc[i][j][0] * s0, acc[i][j][1] * s0);
            *(float2*)&dst[(size_t)(r0 + 8) * ldd + cn] =
                make_float2(acc[i][j][2] * s1, acc[i][j][3] * s1);
        }
    }
}

// ---------------------------------------------------------------------------
// Kernels
// ---------------------------------------------------------------------------
extern __shared__ uint32_t dsm_u32[];

// QKV: C = X @ W_z, one (m-block, z, head) tile per CTA
__global__ __launch_bounds__(256)
void k_qkv(const float* __restrict__ X, const float* __restrict__ Wq,
           const float* __restrict__ Wk, const float* __restrict__ Wv) {
    int z = blockIdx.x >> 5, head = blockIdx.x & 31, bm0 = blockIdx.y * 128;
    const float* W = (z == 0) ? Wq : (z == 1) ? Wk : Wv;
    BSrc bs{W, W, Kdim, (size_t)Nn};
    float acc[2][8][4];
    gemm_tc<Kdim / 16, false, false>(X, Kdim, bm0, bs, head * 128, dsm_u32, acc);
    float* dst = (z == 0) ? g_q  + ((size_t)head * Mm + bm0) * Dd
               : (z == 1) ? g_Kn + ((size_t)head * Mm + bm0) * Dd
                          : g_Vn + ((size_t)head * Mm + bm0) * Dd;
    store_acc(acc, dst, Dd, nullptr);
}

// Scores: S[h][m][l] = q[h] @ K[h]^T; K rows <P from input cache, >=P from g_Kn
__global__ __launch_bounds__(256)
void k_scores(const float* __restrict__ cacheK) {
    int h = blockIdx.z, bm0 = blockIdx.y * 128, l0 = blockIdx.x * 128;
    BSrc bs{cacheK + (size_t)h * Ll * Dd, g_Kn + (size_t)h * Mm * Dd, Pp, (size_t)Dd};
    float acc[2][8][4];
    gemm_tc<Dd / 16, true, false>(g_q + (size_t)h * Mm * Dd, Dd, bm0, bs, l0, dsm_u32, acc);
    store_acc(acc, g_S + ((size_t)h * Mm + bm0) * Ll + l0, Ll, nullptr);
}

// Output: out[m, h*128+d] = (exp(S)[h] @ V[h]) * inv_sum; exp applied in A-loader
__global__ __launch_bounds__(256)
void k_out(const float* __restrict__ cacheV, float* __restrict__ dout) {
    int h = blockIdx.y, bm0 = blockIdx.x * 128;
    BSrc bs{cacheV + (size_t)h * Ll * Dd, g_Vn + (size_t)h * Mm * Dd, Pp, (size_t)Dd};
    float acc[2][8][4];
    gemm_tc<Ll / 16, false, true>(g_S + (size_t)h * Mm * Ll, Ll, bm0, bs, 0, dsm_u32, acc);
    store_acc(acc, dout + (size_t)bm0 * Nn + h * Dd, Nn, g_invs + h * Mm + bm0);
}

// Dual-exp row kernel: reads raw S (no writeback), writes normalized perturb + invs.
__global__ __launch_bounds__(256)
void softmax_rows(const float* __restrict__ noise, float* __restrict__ dout) {
    const int row = blockIdx.x;  // h*Mm + m
    const float* S = g_S + (size_t)row * Ll;
    const float* nz = noise + (size_t)row * Ll;
    float* pout = dout + OUT0 + (size_t)row * Ll;
    __shared__ float ep[Ll];
    __shared__ float r1[256], r2[256];
    const int tid = threadIdx.x;

    float ss = 0.f, sp = 0.f;
    for (int l = tid; l < Ll; l += 256) {
        float s = S[l];
        ss += __expf(s);
        float e2 = __expf((s + nz[l]) * (1.0f / 1.5f));
        ep[l] = e2;
        sp += e2;
    }
    r1[tid] = ss; r2[tid] = sp;
    __syncthreads();
    for (int st = 128; st > 0; st >>= 1) {
        if (tid < st) { r1[tid] += r1[tid + st]; r2[tid] += r2[tid + st]; }
        __syncthreads();
    }
    if (tid == 0) g_invs[row] = 1.0f / r1[0];
    const float ip = 1.0f / r2[0];
    for (int l = tid; l < Ll; l += 256) pout[l] = ep[l] * ip;
}

// ---------------------------------------------------------------------------
// Launch
// ---------------------------------------------------------------------------
extern "C" void kernel_launch(void* const* d_in, const int* in_sizes, int n_in,
                              void* d_out, int out_size) {
    const float* X      = (const float*)d_in[0];
    const float* Wq     = (const float*)d_in[1];
    const float* Wk     = (const float*)d_in[2];
    const float* Wv     = (const float*)d_in[3];
    const float* noise  = (const float*)d_in[4];
    const float* cacheK = (const float*)d_in[5];
    const float* cacheV = (const float*)d_in[6];
    float* out = (float*)d_out;
    (void)in_sizes; (void)n_in; (void)out_size;   // P is static (3584)

    cudaFuncSetAttribute(k_qkv,    cudaFuncAttributeMaxDynamicSharedMemorySize, SMEMSZ);
    cudaFuncSetAttribute(k_scores, cudaFuncAttributeMaxDynamicSharedMemorySize, SMEMSZ);
    cudaFuncSetAttribute(k_out,    cudaFuncAttributeMaxDynamicSharedMemorySize, SMEMSZ);

    k_qkv<<<dim3(96, 4), 256, SMEMSZ>>>(X, Wq, Wk, Wv);
    k_scores<<<dim3(32, 4, 32), 256, SMEMSZ>>>(cacheK);
    softmax_rows<<<Hh * Mm, 256>>>(noise, out);
    k_out<<<dim3(4, 32), 256, SMEMSZ>>>(cacheV, out);
}